// round 2
// baseline (speedup 1.0000x reference)
#include <cuda_runtime.h>
#include <cuda_bf16.h>
#include <cstdint>

// ---------------- device scratch (static allocation only) ----------------
__device__ float d_pw[4096 * 16];        // softmax pattern weights * intensity
__device__ float d_meanpart[4 * 8 * 128];
__device__ int   d_k;

__device__ __forceinline__ float gelu_erf(float v) {
    return 0.5f * v * (1.0f + erff(v * 0.70710678118654752440f));
}
__device__ __forceinline__ float sigmoidf(float v) {
    return 1.0f / (1.0f + expf(-v));
}

// ---------------- Kernel A: per-token selector + intensity ----------------
// grid 512, block 256 (8 warps = 8 tokens per CTA). dynamic smem 109568 B.
__global__ void __launch_bounds__(256) kA(
    const float* __restrict__ x, const float* __restrict__ ctx,
    const float* __restrict__ w1, const float* __restrict__ b1,   // [256,32],[32]
    const float* __restrict__ w2, const float* __restrict__ b2,   // [32,16],[16]
    const float* __restrict__ wi1, const float* __restrict__ bi1, // [256,64],[64]
    const float* __restrict__ wi2, const float* __restrict__ bi2) // [64,1],[1]
{
    extern __shared__ float sm[];
    float* ws1  = sm;            // 8192
    float* ws2  = sm + 8192;     // 512
    float* wi1s = sm + 8704;     // 16384
    float* cs   = sm + 25088;    // 8*256
    float* h1s  = sm + 27136;    // 8*32

    int tid = threadIdx.x;
    for (int i = tid; i < 2048; i += 256) ((float4*)ws1)[i]  = ((const float4*)w1)[i];
    for (int i = tid; i < 128;  i += 256) ((float4*)ws2)[i]  = ((const float4*)w2)[i];
    for (int i = tid; i < 4096; i += 256) ((float4*)wi1s)[i] = ((const float4*)wi1)[i];

    int w = tid >> 5, lane = tid & 31;
    int t = blockIdx.x * 8 + w;

    float4 xv = ((const float4*)x)[t * 32 + lane];
    float4 cv = ((const float4*)ctx)[t * 32 + lane];
    ((float4*)(cs + w * 256))[lane]       = xv;
    ((float4*)(cs + w * 256 + 128))[lane] = cv;
    __syncthreads();

    const float* c = cs + w * 256;

    float acc = b1[lane];
    #pragma unroll 8
    for (int i = 0; i < 256; i++) acc = fmaf(c[i], ws1[i * 32 + lane], acc);
    h1s[w * 32 + lane] = gelu_erf(acc);
    __syncwarp();

    float l = (lane < 16) ? b2[lane] : __int_as_float(0xff800000);
    if (lane < 16) {
        #pragma unroll
        for (int i = 0; i < 32; i++) l = fmaf(h1s[w * 32 + i], ws2[i * 16 + lane], l);
    }
    float m = l;
    #pragma unroll
    for (int off = 8; off >= 1; off >>= 1)
        m = fmaxf(m, __shfl_xor_sync(0xffffffffu, m, off));
    float e = (lane < 16) ? expf(l - m) : 0.0f;
    float s = e;
    #pragma unroll
    for (int off = 8; off >= 1; off >>= 1)
        s += __shfl_xor_sync(0xffffffffu, s, off);
    float pw = e / s;

    float a0 = bi1[lane], a1 = bi1[lane + 32];
    #pragma unroll 8
    for (int i = 0; i < 256; i++) {
        float ci = c[i];
        a0 = fmaf(ci, wi1s[i * 64 + lane], a0);
        a1 = fmaf(ci, wi1s[i * 64 + lane + 32], a1);
    }
    float part = gelu_erf(a0) * wi2[lane] + gelu_erf(a1) * wi2[lane + 32];
    #pragma unroll
    for (int off = 16; off >= 1; off >>= 1)
        part += __shfl_xor_sync(0xffffffffu, part, off);
    float inten = sigmoidf(part + bi2[0]);

    if (lane < 16) d_pw[t * 16 + lane] = pw * inten;
}

// ---------------- Kernel B1: partial batch means of x ----------------
__global__ void kB1(const float* __restrict__ x) {
    int b = blockIdx.x >> 3, chunk = blockIdx.x & 7;
    int d = threadIdx.x;
    const float* p = x + (size_t)(b * 1024 + chunk * 128) * 128 + d;
    float s = 0.0f;
    for (int i = 0; i < 128; i++) s += p[i * 128];
    d_meanpart[blockIdx.x * 128 + d] = s;
}

// ---------------- Kernel B2: window MLP -> global k ----------------
__global__ void kB2(const float* __restrict__ ww1, const float* __restrict__ bw1,
                    const float* __restrict__ ww2, const float* __restrict__ bw2)
{
    __shared__ float mb[128];
    __shared__ float hsm[64];
    int tid = threadIdx.x;
    float winsum = 0.0f;
    for (int b = 0; b < 4; b++) {
        float mv = 0.0f;
        for (int cix = 0; cix < 8; cix++) mv += d_meanpart[(b * 8 + cix) * 128 + tid];
        mb[tid] = mv * (1.0f / 1024.0f);
        __syncthreads();
        if (tid < 64) {
            float a = bw1[tid];
            for (int dd = 0; dd < 128; dd++) a = fmaf(mb[dd], ww1[dd * 64 + tid], a);
            hsm[tid] = gelu_erf(a);
        }
        __syncthreads();
        if (tid == 0) {
            float s2 = bw2[0];
            for (int j = 0; j < 64; j++) s2 = fmaf(hsm[j], ww2[j], s2);
            float wv = sigmoidf(s2);
            winsum += wv * 3840.0f + 256.0f;
        }
        __syncthreads();
    }
    if (tid == 0) {
        float spars = 0.1f * ((winsum * 0.25f) * (1.0f / 4096.0f));
        int k = (int)floorf(16384.0f * spars);
        if (k < 1) k = 1;
        d_k = k;
    }
}

// ---------------- Kernel C: flow GEMM -> d_out (transposed tiling) ----------------
// grid (32 token-groups, 16 col-chunks), block 256. Patterns register-resident.
__global__ void __launch_bounds__(256) kC(const float* __restrict__ pat,
                                          float* __restrict__ out)
{
    __shared__ unsigned long long pwp[2048];  // 128 tokens x 16 patterns, packed (v,v)
    int tid = threadIdx.x;
    int t0 = blockIdx.x * 128;
    int col0 = blockIdx.y * 1024 + tid * 4;

    // patterns for this thread's 4 columns, all 16 patterns -> registers
    const ulonglong2* p2 = (const ulonglong2*)pat;
    unsigned long long pa[16], pb[16];
    #pragma unroll
    for (int p = 0; p < 16; p++) {
        ulonglong2 v = p2[(p * 16384 + col0) >> 2];
        pa[p] = v.x; pb[p] = v.y;
    }

    // pattern weights for 128 tokens
    for (int i = tid; i < 2048; i += 256) {
        unsigned int b = __float_as_uint(d_pw[t0 * 16 + i]);
        pwp[i] = ((unsigned long long)b << 32) | (unsigned long long)b;
    }
    __syncthreads();

    ulonglong2* o2 = (ulonglong2*)out;
    #pragma unroll 2
    for (int t = 0; t < 128; ++t) {
        unsigned long long a0 = 0ULL, a1 = 0ULL;
        const unsigned long long* pwt = &pwp[t * 16];
        #pragma unroll
        for (int p = 0; p < 16; p++) {
            unsigned long long wv = pwt[p];
            asm("fma.rn.f32x2 %0, %1, %2, %3;" : "=l"(a0) : "l"(pa[p]), "l"(wv), "l"(a0));
            asm("fma.rn.f32x2 %0, %1, %2, %3;" : "=l"(a1) : "l"(pb[p]), "l"(wv), "l"(a1));
        }
        ulonglong2 r; r.x = a0; r.y = a1;
        o2[((size_t)(t0 + t) * 16384 + col0) >> 2] = r;
    }
}

// ---------------- Kernel D: exact per-token top-k mask (register-resident) ----------------
__shared__ unsigned int kd_hist[2048];
__shared__ unsigned int kd_cand[2048];
__shared__ unsigned int kd_csum[256];
__shared__ unsigned int kd_sel, kd_rem, kd_cnt;

// select the bin containing the kd_rem-th largest; updates kd_rem. All 512 threads call.
__device__ __forceinline__ void select2048(int tid)
{
    if (tid < 256) {
        unsigned int cs = 0;
        #pragma unroll
        for (int j = 0; j < 8; j++) cs += kd_hist[tid * 8 + j];
        kd_csum[tid] = cs;
    }
    __syncthreads();
    if (tid < 32) {
        unsigned int ws = 0;
        #pragma unroll
        for (int j = 0; j < 8; j++) ws += kd_csum[tid * 8 + j];
        unsigned int sfx = ws;
        #pragma unroll
        for (int off = 1; off <= 16; off <<= 1) {
            unsigned int t2 = __shfl_down_sync(0xffffffffu, sfx, off);
            if (tid + off < 32) sfx += t2;
        }
        unsigned int rem_t = kd_rem;
        unsigned int bal = __ballot_sync(0xffffffffu, sfx >= rem_t);
        int J = 31 - __clz((int)bal);
        if (tid == J) {
            unsigned int rem = rem_t - (sfx - ws);
            int chunk = J * 8;
            for (int cix = J * 8 + 7; cix >= J * 8; --cix) {
                unsigned int cc = kd_csum[cix];
                if (rem <= cc) { chunk = cix; break; }
                rem -= cc;
            }
            int bin = chunk * 8;
            for (int bix = chunk * 8 + 7; bix >= chunk * 8; --bix) {
                unsigned int hc = kd_hist[bix];
                if (rem <= hc) { bin = bix; break; }
                rem -= hc;
            }
            kd_sel = (unsigned int)bin;
            kd_rem = rem;
        }
    }
    __syncthreads();
}

__global__ void __launch_bounds__(512) kD(float* __restrict__ out)
{
    int tid = threadIdx.x;
    int lane = tid & 31;
    float4* g4 = (float4*)(out + (size_t)blockIdx.x * 16384);

    for (int i = tid; i < 2048; i += 512) kd_hist[i] = 0u;
    if (tid == 0) { kd_rem = (unsigned int)d_k; kd_cnt = 0u; }

    // load the whole row into registers (32 values/thread)
    float4 v[8];
    #pragma unroll
    for (int i = 0; i < 8; i++) v[i] = g4[tid + i * 512];
    __syncthreads();

    // pass 0: 2048-bin histogram on top 11 bits of abs-key
    #pragma unroll
    for (int i = 0; i < 8; i++) {
        float vals[4] = {v[i].x, v[i].y, v[i].z, v[i].w};
        #pragma unroll
        for (int j = 0; j < 4; j++) {
            unsigned int key = __float_as_uint(fabsf(vals[j]));
            unsigned int bin = key >> 21;
            unsigned int peers = __match_any_sync(0xffffffffu, bin);
            if ((__ffs(peers) - 1) == lane)
                atomicAdd(&kd_hist[bin], __popc(peers));
        }
    }
    __syncthreads();
    select2048(tid);
    unsigned int sel0 = kd_sel;
    unsigned int cnt0 = kd_hist[sel0];
    unsigned int thrkey;

    if (cnt0 <= 2048u) {
        // compact candidates (exactly cnt0 of them)
        #pragma unroll
        for (int i = 0; i < 8; i++) {
            float vals[4] = {v[i].x, v[i].y, v[i].z, v[i].w};
            #pragma unroll
            for (int j = 0; j < 4; j++) {
                unsigned int key = __float_as_uint(fabsf(vals[j]));
                bool pred = (key >> 21) == sel0;
                unsigned int mask = __ballot_sync(0xffffffffu, pred);
                if (mask) {
                    int leader = __ffs(mask) - 1;
                    unsigned int base = 0;
                    if (lane == leader) base = atomicAdd(&kd_cnt, __popc(mask));
                    base = __shfl_sync(0xffffffffu, base, leader);
                    if (pred)
                        kd_cand[base + __popc(mask & ((1u << lane) - 1u))] = key;
                }
            }
        }
        __syncthreads();

        // pass 1: bits 20..10 over candidates only
        for (int i = tid; i < 2048; i += 512) kd_hist[i] = 0u;
        __syncthreads();
        for (unsigned int i = tid; i < cnt0; i += 512)
            atomicAdd(&kd_hist[(kd_cand[i] >> 10) & 2047u], 1u);
        __syncthreads();
        select2048(tid);
        unsigned int sel1 = kd_sel;
        __syncthreads();

        // pass 2: bits 9..0 over candidates
        for (int i = tid; i < 2048; i += 512) kd_hist[i] = 0u;
        __syncthreads();
        for (unsigned int i = tid; i < cnt0; i += 512) {
            unsigned int key = kd_cand[i];
            if (((key >> 10) & 2047u) == sel1)
                atomicAdd(&kd_hist[key & 1023u], 1u);
        }
        __syncthreads();
        select2048(tid);
        thrkey = (sel0 << 21) | (sel1 << 10) | kd_sel;
    } else {
        // fallback: full-row refinement passes (rare)
        for (int i = tid; i < 2048; i += 512) kd_hist[i] = 0u;
        __syncthreads();
        #pragma unroll
        for (int i = 0; i < 8; i++) {
            float vals[4] = {v[i].x, v[i].y, v[i].z, v[i].w};
            #pragma unroll
            for (int j = 0; j < 4; j++) {
                unsigned int key = __float_as_uint(fabsf(vals[j]));
                if ((key >> 21) == sel0) {
                    unsigned int bin = (key >> 10) & 2047u;
                    unsigned int peers = __match_any_sync(__activemask(), bin);
                    if ((__ffs(peers) - 1) == lane)
                        atomicAdd(&kd_hist[bin], __popc(peers));
                }
            }
        }
        __syncthreads();
        select2048(tid);
        unsigned int p21 = (sel0 << 11) | kd_sel;
        __syncthreads();

        for (int i = tid; i < 2048; i += 512) kd_hist[i] = 0u;
        __syncthreads();
        #pragma unroll
        for (int i = 0; i < 8; i++) {
            float vals[4] = {v[i].x, v[i].y, v[i].z, v[i].w};
            #pragma unroll
            for (int j = 0; j < 4; j++) {
                unsigned int key = __float_as_uint(fabsf(vals[j]));
                if ((key >> 10) == p21) {
                    unsigned int bin = key & 1023u;
                    unsigned int peers = __match_any_sync(__activemask(), bin);
                    if ((__ffs(peers) - 1) == lane)
                        atomicAdd(&kd_hist[bin], __popc(peers));
                }
            }
        }
        __syncthreads();
        select2048(tid);
        thrkey = (p21 << 10) | kd_sel;
    }

    // masked write from registers
    #pragma unroll
    for (int i = 0; i < 8; i++) {
        float4 w = v[i];
        w.x = (__float_as_uint(fabsf(w.x)) >= thrkey) ? w.x : 0.0f;
        w.y = (__float_as_uint(fabsf(w.y)) >= thrkey) ? w.y : 0.0f;
        w.z = (__float_as_uint(fabsf(w.z)) >= thrkey) ? w.z : 0.0f;
        w.w = (__float_as_uint(fabsf(w.w)) >= thrkey) ? w.w : 0.0f;
        g4[tid + i * 512] = w;
    }
}

// ---------------- launch ----------------
extern "C" void kernel_launch(void* const* d_in, const int* in_sizes, int n_in,
                              void* d_out, int out_size)
{
    const float* x    = (const float*)d_in[0];
    const float* ctx  = (const float*)d_in[1];
    const float* pat  = (const float*)d_in[2];
    const float* w1   = (const float*)d_in[3];
    const float* b1   = (const float*)d_in[4];
    const float* w2   = (const float*)d_in[5];
    const float* b2   = (const float*)d_in[6];
    const float* wi1  = (const float*)d_in[7];
    const float* bi1  = (const float*)d_in[8];
    const float* wi2  = (const float*)d_in[9];
    const float* bi2  = (const float*)d_in[10];
    const float* ww1  = (const float*)d_in[11];
    const float* bw1  = (const float*)d_in[12];
    const float* ww2  = (const float*)d_in[13];
    const float* bw2  = (const float*)d_in[14];
    float* out = (float*)d_out;

    cudaFuncSetAttribute(kA, cudaFuncAttributeMaxDynamicSharedMemorySize, 109568);

    kA<<<512, 256, 109568>>>(x, ctx, w1, b1, w2, b2, wi1, bi1, wi2, bi2);
    kB1<<<32, 128>>>(x);
    kB2<<<1, 128>>>(ww1, bw1, ww2, bw2);
    dim3 gC(32, 16);
    kC<<<gC, 256>>>(pat, out);
    kD<<<4096, 512>>>(out);
}

// round 3
// speedup vs baseline: 1.5196x; 1.5196x over previous
#include <cuda_runtime.h>
#include <cuda_bf16.h>
#include <cstdint>

// ---------------- device scratch (static allocation only) ----------------
__device__ float d_pw[4096 * 16];        // softmax pattern weights * intensity
__device__ float d_meanpart[4 * 8 * 128];
__device__ int   d_k;

__device__ __forceinline__ float gelu_erf(float v) {
    return 0.5f * v * (1.0f + erff(v * 0.70710678118654752440f));
}
__device__ __forceinline__ float sigmoidf(float v) {
    return 1.0f / (1.0f + expf(-v));
}

// ---------------- Kernel A: per-token selector + intensity ----------------
__global__ void __launch_bounds__(256) kA(
    const float* __restrict__ x, const float* __restrict__ ctx,
    const float* __restrict__ w1, const float* __restrict__ b1,   // [256,32],[32]
    const float* __restrict__ w2, const float* __restrict__ b2,   // [32,16],[16]
    const float* __restrict__ wi1, const float* __restrict__ bi1, // [256,64],[64]
    const float* __restrict__ wi2, const float* __restrict__ bi2) // [64,1],[1]
{
    extern __shared__ float sm[];
    float* ws1  = sm;            // 8192
    float* ws2  = sm + 8192;     // 512
    float* wi1s = sm + 8704;     // 16384
    float* cs   = sm + 25088;    // 8*256
    float* h1s  = sm + 27136;    // 8*32

    int tid = threadIdx.x;
    for (int i = tid; i < 2048; i += 256) ((float4*)ws1)[i]  = ((const float4*)w1)[i];
    for (int i = tid; i < 128;  i += 256) ((float4*)ws2)[i]  = ((const float4*)w2)[i];
    for (int i = tid; i < 4096; i += 256) ((float4*)wi1s)[i] = ((const float4*)wi1)[i];

    int w = tid >> 5, lane = tid & 31;
    int t = blockIdx.x * 8 + w;

    float4 xv = ((const float4*)x)[t * 32 + lane];
    float4 cv = ((const float4*)ctx)[t * 32 + lane];
    ((float4*)(cs + w * 256))[lane]       = xv;
    ((float4*)(cs + w * 256 + 128))[lane] = cv;
    __syncthreads();

    const float* c = cs + w * 256;

    float acc = b1[lane];
    #pragma unroll 8
    for (int i = 0; i < 256; i++) acc = fmaf(c[i], ws1[i * 32 + lane], acc);
    h1s[w * 32 + lane] = gelu_erf(acc);
    __syncwarp();

    float l = (lane < 16) ? b2[lane] : __int_as_float(0xff800000);
    if (lane < 16) {
        #pragma unroll
        for (int i = 0; i < 32; i++) l = fmaf(h1s[w * 32 + i], ws2[i * 16 + lane], l);
    }
    float m = l;
    #pragma unroll
    for (int off = 8; off >= 1; off >>= 1)
        m = fmaxf(m, __shfl_xor_sync(0xffffffffu, m, off));
    float e = (lane < 16) ? expf(l - m) : 0.0f;
    float s = e;
    #pragma unroll
    for (int off = 8; off >= 1; off >>= 1)
        s += __shfl_xor_sync(0xffffffffu, s, off);
    float pw = e / s;

    float a0 = bi1[lane], a1 = bi1[lane + 32];
    #pragma unroll 8
    for (int i = 0; i < 256; i++) {
        float ci = c[i];
        a0 = fmaf(ci, wi1s[i * 64 + lane], a0);
        a1 = fmaf(ci, wi1s[i * 64 + lane + 32], a1);
    }
    float part = gelu_erf(a0) * wi2[lane] + gelu_erf(a1) * wi2[lane + 32];
    #pragma unroll
    for (int off = 16; off >= 1; off >>= 1)
        part += __shfl_xor_sync(0xffffffffu, part, off);
    float inten = sigmoidf(part + bi2[0]);

    if (lane < 16) d_pw[t * 16 + lane] = pw * inten;
}

// ---------------- Kernel B1: partial batch means of x ----------------
__global__ void kB1(const float* __restrict__ x) {
    int b = blockIdx.x >> 3, chunk = blockIdx.x & 7;
    int d = threadIdx.x;
    const float* p = x + (size_t)(b * 1024 + chunk * 128) * 128 + d;
    float s = 0.0f;
    for (int i = 0; i < 128; i++) s += p[i * 128];
    d_meanpart[blockIdx.x * 128 + d] = s;
}

// ---------------- Kernel B2: window MLP -> global k ----------------
__global__ void kB2(const float* __restrict__ ww1, const float* __restrict__ bw1,
                    const float* __restrict__ ww2, const float* __restrict__ bw2)
{
    __shared__ float mb[128];
    __shared__ float hsm[64];
    int tid = threadIdx.x;
    float winsum = 0.0f;
    for (int b = 0; b < 4; b++) {
        float mv = 0.0f;
        for (int cix = 0; cix < 8; cix++) mv += d_meanpart[(b * 8 + cix) * 128 + tid];
        mb[tid] = mv * (1.0f / 1024.0f);
        __syncthreads();
        if (tid < 64) {
            float a = bw1[tid];
            for (int dd = 0; dd < 128; dd++) a = fmaf(mb[dd], ww1[dd * 64 + tid], a);
            hsm[tid] = gelu_erf(a);
        }
        __syncthreads();
        if (tid == 0) {
            float s2 = bw2[0];
            for (int j = 0; j < 64; j++) s2 = fmaf(hsm[j], ww2[j], s2);
            float wv = sigmoidf(s2);
            winsum += wv * 3840.0f + 256.0f;
        }
        __syncthreads();
    }
    if (tid == 0) {
        float spars = 0.1f * ((winsum * 0.25f) * (1.0f / 4096.0f));
        int k = (int)floorf(16384.0f * spars);
        if (k < 1) k = 1;
        d_k = k;
    }
}

// ---------------- Kernel C: flow GEMM -> d_out (transposed tiling, striped) ----------------
// per stripe: grid (8 token-groups, 16 col-chunks), block 256. Patterns register-resident.
__global__ void __launch_bounds__(256) kC(const float* __restrict__ pat,
                                          float* __restrict__ out, int tok_off)
{
    __shared__ unsigned long long pwp[2048];  // 128 tokens x 16 patterns, packed (v,v)
    int tid = threadIdx.x;
    int t0 = tok_off + blockIdx.x * 128;
    int col0 = blockIdx.y * 1024 + tid * 4;

    const ulonglong2* p2 = (const ulonglong2*)pat;
    unsigned long long pa[16], pb[16];
    #pragma unroll
    for (int p = 0; p < 16; p++) {
        ulonglong2 v = p2[(p * 16384 + col0) >> 2];
        pa[p] = v.x; pb[p] = v.y;
    }

    for (int i = tid; i < 2048; i += 256) {
        unsigned int b = __float_as_uint(d_pw[t0 * 16 + i]);
        pwp[i] = ((unsigned long long)b << 32) | (unsigned long long)b;
    }
    __syncthreads();

    ulonglong2* o2 = (ulonglong2*)out;
    #pragma unroll 2
    for (int t = 0; t < 128; ++t) {
        unsigned long long a0 = 0ULL, a1 = 0ULL;
        const unsigned long long* pwt = &pwp[t * 16];
        #pragma unroll
        for (int p = 0; p < 16; p++) {
            unsigned long long wv = pwt[p];
            asm("fma.rn.f32x2 %0, %1, %2, %3;" : "=l"(a0) : "l"(pa[p]), "l"(wv), "l"(a0));
            asm("fma.rn.f32x2 %0, %1, %2, %3;" : "=l"(a1) : "l"(pb[p]), "l"(wv), "l"(a1));
        }
        ulonglong2 r; r.x = a0; r.y = a1;
        o2[((size_t)(t0 + t) * 16384 + col0) >> 2] = r;
    }
}

// ---------------- Kernel D: exact per-token top-k mask (phase-separated) ----------------
// per stripe: grid 1024, block 512. static smem ~25.3 KB.
__global__ void __launch_bounds__(512) kD(float* __restrict__ out, int tok_off)
{
    __shared__ unsigned int hist[2048];
    __shared__ unsigned int cand[4096];
    __shared__ unsigned int csum[256];
    __shared__ unsigned int s_sel, s_rem, s_cnt;

    int tid = threadIdx.x;
    int lane = tid & 31;
    float4* g4 = (float4*)(out + (size_t)(tok_off + blockIdx.x) * 16384);

    for (int i = tid; i < 2048; i += 512) hist[i] = 0u;
    if (tid == 0) { s_rem = (unsigned int)d_k; s_cnt = 0u; }
    __syncthreads();

    // ---- phase 1: streaming 2048-bin histogram (top 11 bits of abs key) ----
    #pragma unroll
    for (int i = 0; i < 8; i++) {
        float4 v = g4[tid + i * 512];
        atomicAdd(&hist[__float_as_uint(fabsf(v.x)) >> 21], 1u);
        atomicAdd(&hist[__float_as_uint(fabsf(v.y)) >> 21], 1u);
        atomicAdd(&hist[__float_as_uint(fabsf(v.z)) >> 21], 1u);
        atomicAdd(&hist[__float_as_uint(fabsf(v.w)) >> 21], 1u);
    }
    __syncthreads();

    // ---- select bin containing the s_rem-th largest (scan from top) ----
    {
        if (tid < 256) {
            unsigned int cs = 0;
            #pragma unroll
            for (int j = 0; j < 8; j++) cs += hist[tid * 8 + j];
            csum[tid] = cs;
        }
        __syncthreads();
        if (tid < 32) {
            unsigned int ws = 0;
            #pragma unroll
            for (int j = 0; j < 8; j++) ws += csum[tid * 8 + j];
            unsigned int sfx = ws;
            #pragma unroll
            for (int off = 1; off <= 16; off <<= 1) {
                unsigned int t2 = __shfl_down_sync(0xffffffffu, sfx, off);
                if (tid + off < 32) sfx += t2;
            }
            unsigned int rem_t = s_rem;
            unsigned int bal = __ballot_sync(0xffffffffu, sfx >= rem_t);
            int J = 31 - __clz((int)bal);
            if (tid == J) {
                unsigned int rem = rem_t - (sfx - ws);
                int chunk = J * 8;
                for (int cix = J * 8 + 7; cix >= J * 8; --cix) {
                    unsigned int cc = csum[cix];
                    if (rem <= cc) { chunk = cix; break; }
                    rem -= cc;
                }
                int bin = chunk * 8;
                for (int bix = chunk * 8 + 7; bix >= chunk * 8; --bix) {
                    unsigned int hc = hist[bix];
                    if (rem <= hc) { bin = bix; break; }
                    rem -= hc;
                }
                s_sel = (unsigned int)bin;
                s_rem = rem;
            }
        }
        __syncthreads();
    }
    unsigned int sel0 = s_sel;
    unsigned int rem0 = s_rem;
    unsigned int cnt0 = hist[sel0];
    unsigned int thrkey;

    if (cnt0 <= 4096u) {
        // ---- phase 2: re-read (L2-hot), compact candidate keys of selected bin ----
        #pragma unroll
        for (int i = 0; i < 8; i++) {
            float4 v = g4[tid + i * 512];
            unsigned int ks[4] = {__float_as_uint(fabsf(v.x)), __float_as_uint(fabsf(v.y)),
                                  __float_as_uint(fabsf(v.z)), __float_as_uint(fabsf(v.w))};
            #pragma unroll
            for (int j = 0; j < 4; j++) {
                bool pred = (ks[j] >> 21) == sel0;
                unsigned int mask = __ballot_sync(0xffffffffu, pred);
                if (mask) {
                    int leader = __ffs(mask) - 1;
                    unsigned int base = 0;
                    if (lane == leader) base = atomicAdd(&s_cnt, (unsigned int)__popc(mask));
                    base = __shfl_sync(0xffffffffu, base, leader);
                    if (pred)
                        cand[base + __popc(mask & ((1u << lane) - 1u))] = ks[j];
                }
            }
        }
        __syncthreads();

        // ---- phase 3a: bits 20..10 over candidates ----
        for (int i = tid; i < 2048; i += 512) hist[i] = 0u;
        __syncthreads();
        for (unsigned int i = tid; i < cnt0; i += 512)
            atomicAdd(&hist[(cand[i] >> 10) & 2047u], 1u);
        __syncthreads();
        // select again
        {
            if (tid < 256) {
                unsigned int cs = 0;
                #pragma unroll
                for (int j = 0; j < 8; j++) cs += hist[tid * 8 + j];
                csum[tid] = cs;
            }
            __syncthreads();
            if (tid < 32) {
                unsigned int ws = 0;
                #pragma unroll
                for (int j = 0; j < 8; j++) ws += csum[tid * 8 + j];
                unsigned int sfx = ws;
                #pragma unroll
                for (int off = 1; off <= 16; off <<= 1) {
                    unsigned int t2 = __shfl_down_sync(0xffffffffu, sfx, off);
                    if (tid + off < 32) sfx += t2;
                }
                unsigned int rem_t = s_rem;
                unsigned int bal = __ballot_sync(0xffffffffu, sfx >= rem_t);
                int J = 31 - __clz((int)bal);
                if (tid == J) {
                    unsigned int rem = rem_t - (sfx - ws);
                    int chunk = J * 8;
                    for (int cix = J * 8 + 7; cix >= J * 8; --cix) {
                        unsigned int cc = csum[cix];
                        if (rem <= cc) { chunk = cix; break; }
                        rem -= cc;
                    }
                    int bin = chunk * 8;
                    for (int bix = chunk * 8 + 7; bix >= chunk * 8; --bix) {
                        unsigned int hc = hist[bix];
                        if (rem <= hc) { bin = bix; break; }
                        rem -= hc;
                    }
                    s_sel = (unsigned int)bin;
                    s_rem = rem;
                }
            }
            __syncthreads();
        }
        unsigned int sel1 = s_sel;
        __syncthreads();

        // ---- phase 3b: bits 9..0 over candidates ----
        for (int i = tid; i < 1024; i += 512) hist[i] = 0u;
        __syncthreads();
        for (unsigned int i = tid; i < cnt0; i += 512) {
            unsigned int key = cand[i];
            if (((key >> 10) & 2047u) == sel1)
                atomicAdd(&hist[key & 1023u], 1u);
        }
        __syncthreads();
        // final select over 1024 bins
        {
            if (tid < 128) {
                unsigned int cs = 0;
                #pragma unroll
                for (int j = 0; j < 8; j++) cs += hist[tid * 8 + j];
                csum[tid] = cs;
            }
            __syncthreads();
            if (tid < 32) {
                unsigned int ws = 0;
                #pragma unroll
                for (int j = 0; j < 4; j++) ws += csum[tid * 4 + j];
                unsigned int sfx = ws;
                #pragma unroll
                for (int off = 1; off <= 16; off <<= 1) {
                    unsigned int t2 = __shfl_down_sync(0xffffffffu, sfx, off);
                    if (tid + off < 32) sfx += t2;
                }
                unsigned int rem_t = s_rem;
                unsigned int bal = __ballot_sync(0xffffffffu, sfx >= rem_t);
                int J = 31 - __clz((int)bal);
                if (tid == J) {
                    unsigned int rem = rem_t - (sfx - ws);
                    int chunk = J * 4;
                    for (int cix = J * 4 + 3; cix >= J * 4; --cix) {
                        unsigned int cc = csum[cix];
                        if (rem <= cc) { chunk = cix; break; }
                        rem -= cc;
                    }
                    int bin = chunk * 8;
                    for (int bix = chunk * 8 + 7; bix >= chunk * 8; --bix) {
                        unsigned int hc = hist[bix];
                        if (rem <= hc) { bin = bix; break; }
                        rem -= hc;
                    }
                    s_sel = (unsigned int)bin;
                }
            }
            __syncthreads();
        }
        thrkey = (sel0 << 21) | (sel1 << 10) | s_sel;
    } else {
        // ---- fallback (rare): full re-scan refinement, bits 20..10 then 9..0 ----
        if (tid == 0) s_rem = rem0;
        for (int i = tid; i < 2048; i += 512) hist[i] = 0u;
        __syncthreads();
        #pragma unroll
        for (int i = 0; i < 8; i++) {
            float4 v = g4[tid + i * 512];
            float vals[4] = {v.x, v.y, v.z, v.w};
            #pragma unroll
            for (int j = 0; j < 4; j++) {
                unsigned int key = __float_as_uint(fabsf(vals[j]));
                if ((key >> 21) == sel0) atomicAdd(&hist[(key >> 10) & 2047u], 1u);
            }
        }
        __syncthreads();
        {
            if (tid < 256) {
                unsigned int cs = 0;
                #pragma unroll
                for (int j = 0; j < 8; j++) cs += hist[tid * 8 + j];
                csum[tid] = cs;
            }
            __syncthreads();
            if (tid < 32) {
                unsigned int ws = 0;
                #pragma unroll
                for (int j = 0; j < 8; j++) ws += csum[tid * 8 + j];
                unsigned int sfx = ws;
                #pragma unroll
                for (int off = 1; off <= 16; off <<= 1) {
                    unsigned int t2 = __shfl_down_sync(0xffffffffu, sfx, off);
                    if (tid + off < 32) sfx += t2;
                }
                unsigned int rem_t = s_rem;
                unsigned int bal = __ballot_sync(0xffffffffu, sfx >= rem_t);
                int J = 31 - __clz((int)bal);
                if (tid == J) {
                    unsigned int rem = rem_t - (sfx - ws);
                    int chunk = J * 8;
                    for (int cix = J * 8 + 7; cix >= J * 8; --cix) {
                        unsigned int cc = csum[cix];
                        if (rem <= cc) { chunk = cix; break; }
                        rem -= cc;
                    }
                    int bin = chunk * 8;
                    for (int bix = chunk * 8 + 7; bix >= chunk * 8; --bix) {
                        unsigned int hc = hist[bix];
                        if (rem <= hc) { bin = bix; break; }
                        rem -= hc;
                    }
                    s_sel = (unsigned int)bin;
                    s_rem = rem;
                }
            }
            __syncthreads();
        }
        unsigned int p21 = (sel0 << 11) | s_sel;
        __syncthreads();

        for (int i = tid; i < 1024; i += 512) hist[i] = 0u;
        __syncthreads();
        #pragma unroll
        for (int i = 0; i < 8; i++) {
            float4 v = g4[tid + i * 512];
            float vals[4] = {v.x, v.y, v.z, v.w};
            #pragma unroll
            for (int j = 0; j < 4; j++) {
                unsigned int key = __float_as_uint(fabsf(vals[j]));
                if ((key >> 10) == p21) atomicAdd(&hist[key & 1023u], 1u);
            }
        }
        __syncthreads();
        {
            if (tid < 128) {
                unsigned int cs = 0;
                #pragma unroll
                for (int j = 0; j < 8; j++) cs += hist[tid * 8 + j];
                csum[tid] = cs;
            }
            __syncthreads();
            if (tid < 32) {
                unsigned int ws = 0;
                #pragma unroll
                for (int j = 0; j < 4; j++) ws += csum[tid * 4 + j];
                unsigned int sfx = ws;
                #pragma unroll
                for (int off = 1; off <= 16; off <<= 1) {
                    unsigned int t2 = __shfl_down_sync(0xffffffffu, sfx, off);
                    if (tid + off < 32) sfx += t2;
                }
                unsigned int rem_t = s_rem;
                unsigned int bal = __ballot_sync(0xffffffffu, sfx >= rem_t);
                int J = 31 - __clz((int)bal);
                if (tid == J) {
                    unsigned int rem = rem_t - (sfx - ws);
                    int chunk = J * 4;
                    for (int cix = J * 4 + 3; cix >= J * 4; --cix) {
                        unsigned int cc = csum[cix];
                        if (rem <= cc) { chunk = cix; break; }
                        rem -= cc;
                    }
                    int bin = chunk * 8;
                    for (int bix = chunk * 8 + 7; bix >= chunk * 8; --bix) {
                        unsigned int hc = hist[bix];
                        if (rem <= hc) { bin = bix; break; }
                        rem -= hc;
                    }
                    s_sel = (unsigned int)bin;
                }
            }
            __syncthreads();
        }
        thrkey = (p21 << 10) | s_sel;
    }

    // ---- phase 4: re-read (L2-hot), mask, write ----
    #pragma unroll
    for (int i = 0; i < 8; i++) {
        float4 w = g4[tid + i * 512];
        w.x = (__float_as_uint(fabsf(w.x)) >= thrkey) ? w.x : 0.0f;
        w.y = (__float_as_uint(fabsf(w.y)) >= thrkey) ? w.y : 0.0f;
        w.z = (__float_as_uint(fabsf(w.z)) >= thrkey) ? w.z : 0.0f;
        w.w = (__float_as_uint(fabsf(w.w)) >= thrkey) ? w.w : 0.0f;
        g4[tid + i * 512] = w;
    }
}

// ---------------- launch ----------------
extern "C" void kernel_launch(void* const* d_in, const int* in_sizes, int n_in,
                              void* d_out, int out_size)
{
    const float* x    = (const float*)d_in[0];
    const float* ctx  = (const float*)d_in[1];
    const float* pat  = (const float*)d_in[2];
    const float* w1   = (const float*)d_in[3];
    const float* b1   = (const float*)d_in[4];
    const float* w2   = (const float*)d_in[5];
    const float* b2   = (const float*)d_in[6];
    const float* wi1  = (const float*)d_in[7];
    const float* bi1  = (const float*)d_in[8];
    const float* wi2  = (const float*)d_in[9];
    const float* bi2  = (const float*)d_in[10];
    const float* ww1  = (const float*)d_in[11];
    const float* bw1  = (const float*)d_in[12];
    const float* ww2  = (const float*)d_in[13];
    const float* bw2  = (const float*)d_in[14];
    float* out = (float*)d_out;

    cudaFuncSetAttribute(kA, cudaFuncAttributeMaxDynamicSharedMemorySize, 109568);

    kA<<<512, 256, 109568>>>(x, ctx, w1, b1, w2, b2, wi1, bi1, wi2, bi2);
    kB1<<<32, 128>>>(x);
    kB2<<<1, 128>>>(ww1, bw1, ww2, bw2);

    // striped kC/kD so each stripe's flow stays L2-resident between produce/consume
    for (int s = 0; s < 4; s++) {
        dim3 gC(8, 16);
        kC<<<gC, 256>>>(pat, out, s * 1024);
        kD<<<1024, 512>>>(out, s * 1024);
    }
}